// round 8
// baseline (speedup 1.0000x reference)
#include <cuda_runtime.h>
#include <math.h>

#define BB 128
#define TT 512
#define DD 300
#define HH 300
#define NG 1200     // 4*H
#define NGRP 8      // groups of 16 batch rows
#define ROWSG 16    // rows per group
#define NTIL 19     // CTAs per group, 16 units each (19*16 = 304 >= 300)
#define UCTA 16     // units per CTA
#define NCTAS (NGRP*NTIL)   // 152 == GB300 SM count
#define KCH 40      // logical k per chunk (8*40 = 320 >= 300)
#define KST 44      // smem stride per chunk (conflict-free: kc*12 mod 32 distinct)
#define KPADF (8*KST)  // 352 floats per staged h row

typedef unsigned long long u64;

// ---- packed f32x2 helpers (FFMA2: only reachable via PTX) ----
__device__ __forceinline__ u64 f2pack(float lo, float hi) {
    u64 d; asm("mov.b64 %0, {%1, %2};" : "=l"(d) : "f"(lo), "f"(hi)); return d;
}
__device__ __forceinline__ void f2unpack(u64 v, float& lo, float& hi) {
    asm("mov.b64 {%0, %1}, %2;" : "=f"(lo), "=f"(hi) : "l"(v));
}
__device__ __forceinline__ u64 f2fma(u64 a, u64 b, u64 c) {
    u64 d; asm("fma.rn.f32x2 %0, %1, %2, %3;" : "=l"(d) : "l"(a), "l"(b), "l"(c)); return d;
}
__device__ __forceinline__ u64 f2add(u64 a, u64 b) {
    u64 d; asm("add.rn.f32x2 %0, %1, %2;" : "=l"(d) : "l"(a), "l"(b)); return d;
}

// ---- device scratch ----
__device__ float g_h[2][BB*HH];          // double-buffered hidden state
__device__ float g_xz[(size_t)BB*TT*NG]; // precomputed x@Wx + b_lstm
__device__ int   g_flag[NGRP*32];        // per-CTA epoch flags (groups 128B apart)

// ---------------------------------------------------------------------------
__global__ void init_kernel() {
    int i = blockIdx.x * blockDim.x + threadIdx.x;
    if (i < BB*HH) {
        g_h[0][i] = 0.f;
        g_h[1][i] = 0.f;
    }
    if (i < NGRP*32) g_flag[i] = 0;
}

// ---------------------------------------------------------------------------
// precompute: g_xz[b][t][n] = embedding[ids[b][t]] @ W_lstm[0:300, n] + b_lstm[n]
// (FFMA2 version, unchanged from passing round 7)
// ---------------------------------------------------------------------------
__global__ __launch_bounds__(256) void precompute_kernel(
    const int*   __restrict__ ids,
    const int*   __restrict__ lengths,
    const float* __restrict__ emb,
    const float* __restrict__ W,
    const float* __restrict__ bl)
{
    const int b  = blockIdx.z;
    const int t0 = blockIdx.y * 128;
    const int n0 = blockIdx.x * 64;
    if (lengths[b] <= t0) return;

    __shared__ float As[16][128];
    __shared__ float Bs[16][64];
    __shared__ int   toks[128];

    const int tid = threadIdx.x;
    if (tid < 128) toks[tid] = ids[b*TT + t0 + tid];

    const int tx = tid & 15;
    const int ty = tid >> 4;
    u64 acc2[4][4];
    #pragma unroll
    for (int i = 0; i < 4; i++)
        #pragma unroll
        for (int j = 0; j < 4; j++) acc2[i][j] = 0ull;

    for (int k0 = 0; k0 < 300; k0 += 16) {
        __syncthreads();
        for (int l = tid; l < 512; l += 256) {
            int r  = l >> 2;
            int kq = l & 3;
            int k  = k0 + kq * 4;
            float4 v = make_float4(0.f, 0.f, 0.f, 0.f);
            if (k < 300) v = *(const float4*)(emb + (size_t)toks[r]*DD + k);
            As[kq*4+0][r] = v.x;
            As[kq*4+1][r] = v.y;
            As[kq*4+2][r] = v.z;
            As[kq*4+3][r] = v.w;
        }
        {
            int l  = tid;
            int kk = l >> 4;
            int q  = l & 15;
            int k  = k0 + kk;
            int n  = n0 + q * 4;
            float4 v = make_float4(0.f, 0.f, 0.f, 0.f);
            if (k < 300 && n < NG) v = *(const float4*)(W + (size_t)k*NG + n);
            *(float4*)&Bs[kk][q*4] = v;
        }
        __syncthreads();
        #pragma unroll
        for (int kk = 0; kk < 16; kk++) {
            float4 bv = *(const float4*)&Bs[kk][tx*4];
            u64 b0 = f2pack(bv.x, bv.x);
            u64 b1 = f2pack(bv.y, bv.y);
            u64 b2 = f2pack(bv.z, bv.z);
            u64 b3 = f2pack(bv.w, bv.w);
            const u64* a2 = (const u64*)&As[kk][ty*8];
            #pragma unroll
            for (int mp = 0; mp < 4; mp++) {
                u64 av = a2[mp];
                acc2[mp][0] = f2fma(av, b0, acc2[mp][0]);
                acc2[mp][1] = f2fma(av, b1, acc2[mp][1]);
                acc2[mp][2] = f2fma(av, b2, acc2[mp][2]);
                acc2[mp][3] = f2fma(av, b3, acc2[mp][3]);
            }
        }
    }

    const int n = n0 + tx * 4;
    if (n < NG) {
        float4 blv = *(const float4*)(bl + n);
        #pragma unroll
        for (int mp = 0; mp < 4; mp++) {
            float x0,x1,y0,y1,z0,z1,q0,q1;
            f2unpack(acc2[mp][0], x0, x1);
            f2unpack(acc2[mp][1], y0, y1);
            f2unpack(acc2[mp][2], z0, z1);
            f2unpack(acc2[mp][3], q0, q1);
            int t = t0 + ty*8 + 2*mp;
            float4 o0 = make_float4(x0+blv.x, y0+blv.y, z0+blv.z, q0+blv.w);
            float4 o1 = make_float4(x1+blv.x, y1+blv.y, z1+blv.z, q1+blv.w);
            *(float4*)(g_xz + ((size_t)b*TT + t  )*NG + n) = o0;
            *(float4*)(g_xz + ((size_t)b*TT + t+1)*NG + n) = o1;
        }
    }
}

// ---------------------------------------------------------------------------
// persistent recurrence kernel v4.
// grid = 152 CTAs = 8 groups (16 rows) x 19 CTAs (16 units each), 256 thr.
// Matmul: warp wid owns units ua=u0+2*wid, ub=ua+1; lane = kc*4+gg.
//   Thread holds W for BOTH units of its (kc-chunk, gate): 40 f32x2 regs.
//   h loaded once per (m, k-quad) -> reused for 2 units (crossbar halved).
//   Chunk kc lives at smem offset kc*44 (words): kc*12 mod 32 distinct ->
//   conflict-free LDS.128 across a warp.
// Barrier: per-group epoch flags. Arrive: bar.sync -> st.release.gpu flag=t+1
//   (publishes all CTA threads' prior weak stores at gpu scope: the canonical
//   cooperative-groups grid.sync pattern). Wait: warp 0 polls 19 flags with
//   one coalesced ld.acquire.gpu + __all_sync. No atomics, no nanosleep.
// Epilogue: thread (mm=tid>>4, uu=tid&15) owns (row m0+mm, unit u0+uu);
//   c register-resident. Buffer-parity invariant: group retires at its
//   maxlen; final state in g_h[maxlen&1] (final_kernel recomputes per 16-row
//   group).
// ---------------------------------------------------------------------------
__global__ __launch_bounds__(256) void lstm_persistent(
    const float* __restrict__ W,
    const int*   __restrict__ lengths)
{
    __shared__ float hs[ROWSG*KPADF];   // 16 x 352
    __shared__ float zsm[ROWSG*64];     // 16 rows x (16 units * 4 gates)
    __shared__ int   sl[ROWSG];

    const int gidx  = blockIdx.x / NTIL;   // group
    const int ntile = blockIdx.x % NTIL;
    const int u0    = ntile * UCTA;
    const int m0    = gidx * ROWSG;
    const int tid   = threadIdx.x;
    const int wid   = tid >> 5;
    const int lane  = tid & 31;
    const int kc    = lane >> 2;           // k-chunk 0..7
    const int gg    = lane & 3;            // gate
    const int ua    = u0 + 2*wid;          // this thread's two units
    const int ub    = ua + 1;

    // epilogue mapping: 1 output per thread
    const int  e_mm   = tid >> 4;
    const int  e_uu   = tid & 15;
    const int  e_u    = u0 + e_uu;
    const int  e_b    = m0 + e_mm;
    const bool e_uval = (e_u < HH);
    const int  e_hsu  = e_mm*KPADF + (e_u/KCH)*KST + (e_u % KCH);

    if (tid < ROWSG) sl[tid] = lengths[m0 + tid];

    // W slice -> registers (step-invariant)
    u64 w2a[20], w2b[20];
    {
        #pragma unroll
        for (int i = 0; i < 20; i++) {
            int k0 = kc*KCH + 2*i;
            int k1 = k0 + 1;
            float a_lo = (k0 < HH && ua < HH) ? W[(size_t)(HH + k0)*NG + gg*HH + ua] : 0.f;
            float a_hi = (k1 < HH && ua < HH) ? W[(size_t)(HH + k1)*NG + gg*HH + ua] : 0.f;
            float b_lo = (k0 < HH && ub < HH) ? W[(size_t)(HH + k0)*NG + gg*HH + ub] : 0.f;
            float b_hi = (k1 < HH && ub < HH) ? W[(size_t)(HH + k1)*NG + gg*HH + ub] : 0.f;
            w2a[i] = f2pack(a_lo, a_hi);
            w2b[i] = f2pack(b_lo, b_hi);
        }
    }
    __syncthreads();
    int maxlen = 0;
    #pragma unroll
    for (int i = 0; i < ROWSG; i++) maxlen = max(maxlen, sl[i]);
    const int e_len = sl[e_mm];

    int* myflag = &g_flag[gidx*32 + ntile];
    const bool poll_has = (tid < NTIL);
    int* pollp = &g_flag[gidx*32 + (poll_has ? tid : 0)];

    float c_reg = 0.f;   // cell state for (e_b, e_u)

    for (int t = 0; t < maxlen; t++) {
        const float* hread  = g_h[t & 1];
        float*       hwrite = g_h[(t & 1) ^ 1];
        const bool   act    = e_uval && (t < e_len);

        // prefetch xz (epilogue operands; DRAM latency hidden behind matmul)
        const float* xzp = g_xz + ((size_t)e_b*TT + t)*NG + e_u;
        float pf0 = act ? __ldcg(xzp + 0*HH) : 0.f;
        float pf1 = act ? __ldcg(xzp + 1*HH) : 0.f;
        float pf2 = act ? __ldcg(xzp + 2*HH) : 0.f;
        float pf3 = act ? __ldcg(xzp + 3*HH) : 0.f;

        // stage h tile: 16 rows x 320 (chunked at stride 44 words)
        #pragma unroll
        for (int s = 0; s < 5; s++) {
            int l   = tid + s*256;          // 0..1279
            int m   = l / 80;
            int q   = l - m*80;
            int kk  = q / 10;
            int ii  = q - kk*10;
            int k   = kk*KCH + ii*4;
            float4 v = make_float4(0.f, 0.f, 0.f, 0.f);
            if (k < HH) v = __ldcg((const float4*)(hread + (size_t)(m0+m)*HH + k));
            *(float4*)&hs[m*KPADF + kk*KST + ii*4] = v;
        }
        __syncthreads();

        // matmul: per row m, partial dots over this thread's chunk, 2 units
        #pragma unroll 2
        for (int m = 0; m < ROWSG; m++) {
            const float* hb = hs + m*KPADF + kc*KST;
            u64 A0 = 0ull, A1 = 0ull, B0 = 0ull, B1 = 0ull;
            #pragma unroll
            for (int i = 0; i < 10; i++) {
                float4 hv = *(const float4*)(hb + i*4);
                u64 h01 = f2pack(hv.x, hv.y);
                u64 h23 = f2pack(hv.z, hv.w);
                A0 = f2fma(w2a[2*i],   h01, A0);
                A1 = f2fma(w2a[2*i+1], h23, A1);
                B0 = f2fma(w2b[2*i],   h01, B0);
                B1 = f2fma(w2b[2*i+1], h23, B1);
            }
            float al, ah, bl_, bh;
            f2unpack(f2add(A0, A1), al, ah);
            f2unpack(f2add(B0, B1), bl_, bh);
            float va = al + ah;
            float vb = bl_ + bh;
            va += __shfl_xor_sync(0xffffffffu, va, 4);
            vb += __shfl_xor_sync(0xffffffffu, vb, 4);
            va += __shfl_xor_sync(0xffffffffu, va, 8);
            vb += __shfl_xor_sync(0xffffffffu, vb, 8);
            va += __shfl_xor_sync(0xffffffffu, va, 16);
            vb += __shfl_xor_sync(0xffffffffu, vb, 16);
            if (kc == 0) {
                zsm[m*64 + (2*wid)*4 + gg] = va;
                zsm[m*64 + (2*wid+1)*4 + gg] = vb;
            }
        }
        __syncthreads();

        // epilogue: one (row, unit) per thread
        if (act) {
            float4 zv = *(const float4*)&zsm[e_mm*64 + e_uu*4];
            float zi = zv.x + pf0;
            float zj = zv.y + pf1;
            float zf = zv.z + pf2;
            float zo = zv.w + pf3;
            float si = 1.f / (1.f + __expf(-zi));
            float sf = 1.f / (1.f + __expf(-(zf + 1.f)));  // FORGET_BIAS=1
            float so = 1.f / (1.f + __expf(-zo));
            float tj = tanhf(zj);
            c_reg = c_reg * sf + si * tj;
            float hnew = tanhf(c_reg) * so;
            __stcg(&hwrite[e_b*HH + e_u], hnew);
        } else if (e_uval) {
            __stcg(&hwrite[e_b*HH + e_u], hs[e_hsu]);   // carry frozen state
        }

        // --- group barrier: flags + tight spin ---
        __syncthreads();                    // all stores program-ordered before release
        if (tid == 0) {
            asm volatile("st.release.gpu.s32 [%0], %1;"
                         :: "l"(myflag), "r"(t + 1) : "memory");
        }
        if (tid < 32) {
            const int target = t + 1;
            int v;
            do {
                asm volatile("ld.acquire.gpu.s32 %0, [%1];"
                             : "=r"(v) : "l"(pollp) : "memory");
            } while (!__all_sync(0xffffffffu, !poll_has || (v >= target)));
        }
        __syncthreads();
    }
}

// ---------------------------------------------------------------------------
// final: logits + mean NLL. Row b's final h is in buffer (group maxlen & 1),
// group = b's 16-row block.
// ---------------------------------------------------------------------------
__global__ void final_kernel(
    const float* __restrict__ Wd,
    const float* __restrict__ bd,
    const int*   __restrict__ labels,
    const int*   __restrict__ lengths,
    float*       __restrict__ out,
    int out_size)
{
    __shared__ float red[128];
    __shared__ int   slen[128];
    __shared__ float wd_s[900];
    int b = threadIdx.x;
    slen[b] = lengths[b];
    for (int i = b; i < 900; i += 128) wd_s[i] = Wd[i];
    __syncthreads();

    int tile0 = b & ~(ROWSG - 1);
    int maxlen = 0;
    #pragma unroll
    for (int i = 0; i < ROWSG; i++) maxlen = max(maxlen, slen[tile0 + i]);
    const float* h = g_h[maxlen & 1] + b*HH;

    float a0 = bd[0], a1 = bd[1], a2 = bd[2];
    #pragma unroll 5
    for (int k = 0; k < HH; k += 4) {
        float4 hv = *(const float4*)(h + k);
        a0 += hv.x*wd_s[(k+0)*3+0] + hv.y*wd_s[(k+1)*3+0]
            + hv.z*wd_s[(k+2)*3+0] + hv.w*wd_s[(k+3)*3+0];
        a1 += hv.x*wd_s[(k+0)*3+1] + hv.y*wd_s[(k+1)*3+1]
            + hv.z*wd_s[(k+2)*3+1] + hv.w*wd_s[(k+3)*3+1];
        a2 += hv.x*wd_s[(k+0)*3+2] + hv.y*wd_s[(k+1)*3+2]
            + hv.z*wd_s[(k+2)*3+2] + hv.w*wd_s[(k+3)*3+2];
    }
    float mx  = fmaxf(a0, fmaxf(a1, a2));
    float lse = mx + logf(expf(a0 - mx) + expf(a1 - mx) + expf(a2 - mx));
    int   lab = labels[b];
    float sel = (lab == 0) ? a0 : ((lab == 1) ? a1 : a2);
    float nll = lse - sel;

    int off = (out_size >= 385) ? 1 : 0;
    if (out_size >= 384) {
        out[off + b*3 + 0] = a0;
        out[off + b*3 + 1] = a1;
        out[off + b*3 + 2] = a2;
    }
    red[b] = nll;
    __syncthreads();
    for (int s = 64; s; s >>= 1) {
        if (b < s) red[b] += red[b + s];
        __syncthreads();
    }
    if (b == 0 && (off == 1 || out_size < 384)) out[0] = red[0] * (1.f / 128.f);
}

// ---------------------------------------------------------------------------
extern "C" void kernel_launch(void* const* d_in, const int* in_sizes, int n_in,
                              void* d_out, int out_size)
{
    const int*   ids     = (const int*)  d_in[0];
    const int*   lengths = (const int*)  d_in[1];
    const int*   labels  = (const int*)  d_in[2];
    const float* emb     = (const float*)d_in[3];
    const float* W       = (const float*)d_in[4];
    const float* bl      = (const float*)d_in[5];
    const float* Wd      = (const float*)d_in[6];
    const float* bd      = (const float*)d_in[7];
    float* out = (float*)d_out;

    init_kernel<<<(BB*HH + 255)/256, 256>>>();
    precompute_kernel<<<dim3(19, 4, BB), 256>>>(ids, lengths, emb, W, bl);
    lstm_persistent<<<NCTAS, 256>>>(W, lengths);
    final_kernel<<<1, 128>>>(Wd, bd, labels, lengths, out, out_size);
}

// round 9
// speedup vs baseline: 1.2967x; 1.2967x over previous
#include <cuda_runtime.h>
#include <math.h>

#define BB 128
#define TT 512
#define DD 300
#define HH 300
#define NG 1200     // 4*H
#define NBLK 8      // CTA blocks of 19; block j hosts groups 2j, 2j+1
#define NTIL 19     // CTAs per group (16 units each: 19*16 = 304 >= 300)
#define NGRP 16     // groups of 8 batch rows
#define ROWSG 8
#define UCTA 16
#define NCTAS (NBLK*NTIL)   // 152 == GB300 SM count
#define KCH 40      // logical k per chunk (8*40 = 320 >= 300)
#define KST 44      // smem stride per chunk (banks kc*12 mod 32 distinct)
#define KPADF (8*KST)  // 352 floats per staged h row

typedef unsigned long long u64;

// ---- packed f32x2 helpers ----
__device__ __forceinline__ u64 f2pack(float lo, float hi) {
    u64 d; asm("mov.b64 %0, {%1, %2};" : "=l"(d) : "f"(lo), "f"(hi)); return d;
}
__device__ __forceinline__ void f2unpack(u64 v, float& lo, float& hi) {
    asm("mov.b64 {%0, %1}, %2;" : "=f"(lo), "=f"(hi) : "l"(v));
}
__device__ __forceinline__ u64 f2fma(u64 a, u64 b, u64 c) {
    u64 d; asm("fma.rn.f32x2 %0, %1, %2, %3;" : "=l"(d) : "l"(a), "l"(b), "l"(c)); return d;
}
__device__ __forceinline__ u64 f2add(u64 a, u64 b) {
    u64 d; asm("add.rn.f32x2 %0, %1, %2;" : "=l"(d) : "l"(a), "l"(b)); return d;
}

// half-CTA barrier (ids 1 and 2; 128 threads each)
__device__ __forceinline__ void barh(int half) {
    asm volatile("bar.sync %0, 128;" :: "r"(half + 1) : "memory");
}

// ---- device scratch ----
__device__ float g_h[2][BB*HH];          // double-buffered hidden state
__device__ float g_xz[(size_t)BB*TT*NG]; // precomputed x@Wx + b_lstm
__device__ int   g_flag[NGRP*32];        // per-CTA epoch flags (groups 128B apart)

// ---------------------------------------------------------------------------
__global__ void init_kernel() {
    int i = blockIdx.x * blockDim.x + threadIdx.x;
    if (i < BB*HH) {
        g_h[0][i] = 0.f;
        g_h[1][i] = 0.f;
    }
    if (i < NGRP*32) g_flag[i] = 0;
}

// ---------------------------------------------------------------------------
// precompute: g_xz[b][t][n] = embedding[ids[b][t]] @ W_lstm[0:300, n] + b_lstm[n]
// (unchanged from passing round 7/8)
// ---------------------------------------------------------------------------
__global__ __launch_bounds__(256) void precompute_kernel(
    const int*   __restrict__ ids,
    const int*   __restrict__ lengths,
    const float* __restrict__ emb,
    const float* __restrict__ W,
    const float* __restrict__ bl)
{
    const int b  = blockIdx.z;
    const int t0 = blockIdx.y * 128;
    const int n0 = blockIdx.x * 64;
    if (lengths[b] <= t0) return;

    __shared__ float As[16][128];
    __shared__ float Bs[16][64];
    __shared__ int   toks[128];

    const int tid = threadIdx.x;
    if (tid < 128) toks[tid] = ids[b*TT + t0 + tid];

    const int tx = tid & 15;
    const int ty = tid >> 4;
    u64 acc2[4][4];
    #pragma unroll
    for (int i = 0; i < 4; i++)
        #pragma unroll
        for (int j = 0; j < 4; j++) acc2[i][j] = 0ull;

    for (int k0 = 0; k0 < 300; k0 += 16) {
        __syncthreads();
        for (int l = tid; l < 512; l += 256) {
            int r  = l >> 2;
            int kq = l & 3;
            int k  = k0 + kq * 4;
            float4 v = make_float4(0.f, 0.f, 0.f, 0.f);
            if (k < 300) v = *(const float4*)(emb + (size_t)toks[r]*DD + k);
            As[kq*4+0][r] = v.x;
            As[kq*4+1][r] = v.y;
            As[kq*4+2][r] = v.z;
            As[kq*4+3][r] = v.w;
        }
        {
            int l  = tid;
            int kk = l >> 4;
            int q  = l & 15;
            int k  = k0 + kk;
            int n  = n0 + q * 4;
            float4 v = make_float4(0.f, 0.f, 0.f, 0.f);
            if (k < 300 && n < NG) v = *(const float4*)(W + (size_t)k*NG + n);
            *(float4*)&Bs[kk][q*4] = v;
        }
        __syncthreads();
        #pragma unroll
        for (int kk = 0; kk < 16; kk++) {
            float4 bv = *(const float4*)&Bs[kk][tx*4];
            u64 b0 = f2pack(bv.x, bv.x);
            u64 b1 = f2pack(bv.y, bv.y);
            u64 b2 = f2pack(bv.z, bv.z);
            u64 b3 = f2pack(bv.w, bv.w);
            const u64* a2 = (const u64*)&As[kk][ty*8];
            #pragma unroll
            for (int mp = 0; mp < 4; mp++) {
                u64 av = a2[mp];
                acc2[mp][0] = f2fma(av, b0, acc2[mp][0]);
                acc2[mp][1] = f2fma(av, b1, acc2[mp][1]);
                acc2[mp][2] = f2fma(av, b2, acc2[mp][2]);
                acc2[mp][3] = f2fma(av, b3, acc2[mp][3]);
            }
        }
    }

    const int n = n0 + tx * 4;
    if (n < NG) {
        float4 blv = *(const float4*)(bl + n);
        #pragma unroll
        for (int mp = 0; mp < 4; mp++) {
            float x0,x1,y0,y1,z0,z1,q0,q1;
            f2unpack(acc2[mp][0], x0, x1);
            f2unpack(acc2[mp][1], y0, y1);
            f2unpack(acc2[mp][2], z0, z1);
            f2unpack(acc2[mp][3], q0, q1);
            int t = t0 + ty*8 + 2*mp;
            float4 o0 = make_float4(x0+blv.x, y0+blv.y, z0+blv.z, q0+blv.w);
            float4 o1 = make_float4(x1+blv.x, y1+blv.y, z1+blv.z, q1+blv.w);
            *(float4*)(g_xz + ((size_t)b*TT + t  )*NG + n) = o0;
            *(float4*)(g_xz + ((size_t)b*TT + t+1)*NG + n) = o1;
        }
    }
}

// ---------------------------------------------------------------------------
// persistent recurrence kernel v5: warp-specialized DUAL-GROUP per CTA.
// grid = 152 CTAs = 8 blocks x 19 CTAs; block j hosts group 2j (warps 0-3)
// and group 2j+1 (warps 4-7). Each half (128 thr) runs an independent
// 8-row x 16-unit recurrence with its own named barrier (bar.sync 1/2) and
// its own flag set — while one half waits in its release->detect window,
// the other half's warps issue compute on the same SMSPs (latency hiding).
// Matmul per half: warp w4 owns units u0+4*w4..+3; lane = kc*4+gate;
//   W held in 80 u64 regs/thread; h read as LDS.64 (no packing).
// Buffer-parity invariant per group of 8 rows: group retires at its maxlen;
// final state in g_h[maxlen&1].
// ---------------------------------------------------------------------------
__global__ __launch_bounds__(256) void lstm_persistent(
    const float* __restrict__ W,
    const int*   __restrict__ lengths)
{
    __shared__ __align__(16) float hs2[2][ROWSG*KPADF];   // per-half h tiles
    __shared__ __align__(16) float zs2[2][ROWSG*64];      // per-half z tiles
    __shared__ int sl[16];

    const int tid  = threadIdx.x;
    const int half = tid >> 7;
    const int t128 = tid & 127;
    const int w4   = t128 >> 5;            // warp within half (0..3)
    const int lane = tid & 31;
    const int kc   = lane >> 2;            // k-chunk 0..7
    const int gg   = lane & 3;             // gate

    const int jblk  = blockIdx.x / NTIL;
    const int ntile = blockIdx.x % NTIL;
    const int gid   = 2*jblk + half;
    const int m0    = gid * ROWSG;
    const int u0    = ntile * UCTA;

    if (tid < 16) sl[tid] = lengths[jblk*16 + tid];

    // W -> registers: 4 units x 20 f32x2 per thread (step-invariant)
    u64 w2[4][20];
    #pragma unroll
    for (int jj = 0; jj < 4; jj++) {
        int  u  = u0 + 4*w4 + jj;
        bool uv = (u < HH);
        int  col = gg*HH + (uv ? u : 0);
        #pragma unroll
        for (int i = 0; i < 20; i++) {
            int k0 = kc*KCH + 2*i;
            float lo = (uv && k0     < HH) ? W[(size_t)(HH + k0    )*NG + col] : 0.f;
            float hi = (uv && k0 + 1 < HH) ? W[(size_t)(HH + k0 + 1)*NG + col] : 0.f;
            w2[jj][i] = f2pack(lo, hi);
        }
    }
    __syncthreads();   // sl visible; after this the halves never co-sync

    int maxlen = 0;
    #pragma unroll
    for (int i = 0; i < ROWSG; i++) maxlen = max(maxlen, sl[half*ROWSG + i]);

    // epilogue mapping: 1 (row, unit) per thread within the half
    const int  e_mm   = t128 >> 4;
    const int  e_uu   = t128 & 15;
    const int  e_u    = u0 + e_uu;
    const int  e_b    = m0 + e_mm;
    const bool e_uval = (e_u < HH);
    const int  e_len  = sl[half*ROWSG + e_mm];
    const int  e_hsoff = e_mm*KPADF + (e_u/KCH)*KST + (e_u % KCH);

    float* hsh = hs2[half];
    float* zsh = zs2[half];
    int*   flagbase = &g_flag[gid*32];
    int*   myflag   = flagbase + ntile;

    float c_reg = 0.f;   // cell state for (e_b, e_u)

    for (int t = 0; t < maxlen; t++) {
        const float* hread  = g_h[t & 1];
        float*       hwrite = g_h[(t & 1) ^ 1];
        const bool   act    = e_uval && (t < e_len);

        // prefetch xz (epilogue operands; DRAM latency hidden behind matmul)
        const float* xzp = g_xz + ((size_t)e_b*TT + t)*NG + e_u;
        float pf0 = act ? __ldcg(xzp + 0*HH) : 0.f;
        float pf1 = act ? __ldcg(xzp + 1*HH) : 0.f;
        float pf2 = act ? __ldcg(xzp + 2*HH) : 0.f;
        float pf3 = act ? __ldcg(xzp + 3*HH) : 0.f;

        // stage h tile: 8 rows x 320 (chunks of 40 at stride 44 words)
        #pragma unroll
        for (int s = 0; s < 5; s++) {
            int l  = t128 + s*128;          // 0..639
            int m  = l / 80;
            int q  = l - m*80;
            int kk = q / 10;
            int ii = q - kk*10;
            int k  = kk*KCH + ii*4;
            float4 v = make_float4(0.f, 0.f, 0.f, 0.f);
            if (k < HH) v = __ldcg((const float4*)(hread + (size_t)(m0+m)*HH + k));
            *(float4*)&hsh[m*KPADF + kk*KST + ii*4] = v;
        }
        barh(half);

        // matmul: per row, 4 unit dot-products over this thread's chunk
        #pragma unroll 1
        for (int m = 0; m < ROWSG; m++) {
            const u64* h2 = (const u64*)(hsh + m*KPADF + kc*KST);
            u64 s0=0ull, s1=0ull, s2=0ull, s3=0ull;
            u64 r0=0ull, r1=0ull, r2=0ull, r3=0ull;
            #pragma unroll
            for (int i = 0; i < 20; i += 2) {
                u64 ha = h2[i];
                u64 hb = h2[i+1];
                s0 = f2fma(w2[0][i], ha, s0); r0 = f2fma(w2[0][i+1], hb, r0);
                s1 = f2fma(w2[1][i], ha, s1); r1 = f2fma(w2[1][i+1], hb, r1);
                s2 = f2fma(w2[2][i], ha, s2); r2 = f2fma(w2[2][i+1], hb, r2);
                s3 = f2fma(w2[3][i], ha, s3); r3 = f2fma(w2[3][i+1], hb, r3);
            }
            float v0, v1, v2, v3;
            { float lo, hi; f2unpack(f2add(s0, r0), lo, hi); v0 = lo + hi; }
            { float lo, hi; f2unpack(f2add(s1, r1), lo, hi); v1 = lo + hi; }
            { float lo, hi; f2unpack(f2add(s2, r2), lo, hi); v2 = lo + hi; }
            { float lo, hi; f2unpack(f2add(s3, r3), lo, hi); v3 = lo + hi; }
            #pragma unroll
            for (int o = 4; o <= 16; o <<= 1) {
                v0 += __shfl_xor_sync(0xffffffffu, v0, o);
                v1 += __shfl_xor_sync(0xffffffffu, v1, o);
                v2 += __shfl_xor_sync(0xffffffffu, v2, o);
                v3 += __shfl_xor_sync(0xffffffffu, v3, o);
            }
            if (kc == 0) {
                zsh[m*64 + (4*w4 + 0)*4 + gg] = v0;
                zsh[m*64 + (4*w4 + 1)*4 + gg] = v1;
                zsh[m*64 + (4*w4 + 2)*4 + gg] = v2;
                zsh[m*64 + (4*w4 + 3)*4 + gg] = v3;
            }
        }
        barh(half);

        // epilogue: one (row, unit) per thread
        if (act) {
            float4 zv = *(const float4*)&zsh[e_mm*64 + e_uu*4];
            float zi = zv.x + pf0;
            float zj = zv.y + pf1;
            float zf = zv.z + pf2;
            float zo = zv.w + pf3;
            float si = 1.f / (1.f + __expf(-zi));
            float sf = 1.f / (1.f + __expf(-(zf + 1.f)));  // FORGET_BIAS=1
            float so = 1.f / (1.f + __expf(-zo));
            float tj = tanhf(zj);
            c_reg = c_reg * sf + si * tj;
            float hnew = tanhf(c_reg) * so;
            __stcg(&hwrite[e_b*HH + e_u], hnew);
        } else if (e_uval) {
            __stcg(&hwrite[e_b*HH + e_u], hsh[e_hsoff]);   // carry frozen state
        }

        // group barrier (per half): release -> flags -> acquire-poll
        barh(half);
        if (t128 == 0) {
            asm volatile("st.release.gpu.s32 [%0], %1;"
                         :: "l"(myflag), "r"(t + 1) : "memory");
        }
        if (t128 < 32) {
            const bool has = (lane < NTIL);
            int* pp = flagbase + (has ? lane : 0);
            const int target = t + 1;
            int v;
            do {
                asm volatile("ld.acquire.gpu.s32 %0, [%1];"
                             : "=r"(v) : "l"(pp) : "memory");
            } while (!__all_sync(0xffffffffu, !has || (v >= target)));
        }
        barh(half);
    }
}

// ---------------------------------------------------------------------------
// final: logits + mean NLL. Row b's final h is in buffer (group maxlen & 1),
// group = b's 8-row block.
// ---------------------------------------------------------------------------
__global__ void final_kernel(
    const float* __restrict__ Wd,
    const float* __restrict__ bd,
    const int*   __restrict__ labels,
    const int*   __restrict__ lengths,
    float*       __restrict__ out,
    int out_size)
{
    __shared__ float red[128];
    __shared__ int   slen[128];
    __shared__ float wd_s[900];
    int b = threadIdx.x;
    slen[b] = lengths[b];
    for (int i = b; i < 900; i += 128) wd_s[i] = Wd[i];
    __syncthreads();

    int tile0 = b & ~(ROWSG - 1);
    int maxlen = 0;
    #pragma unroll
    for (int i = 0; i < ROWSG; i++) maxlen = max(maxlen, slen[tile0 + i]);
    const float* h = g_h[maxlen & 1] + b*HH;

    float a0 = bd[0], a1 = bd[1], a2 = bd[2];
    #pragma unroll 5
    for (int k = 0; k < HH; k += 4) {
        float4 hv = *(const float4*)(h + k);
        a0 += hv.x*wd_s[(k+0)*3+0] + hv.y*wd_s[(k+1)*3+0]
            + hv.z*wd_s[(k+2)*3+0] + hv.w*wd_s[(k+3)*3+0];
        a1 += hv.x*wd_s[(k+0)*3+1] + hv.y*wd_s[(k+1)*3+1]
            + hv.z*wd_s[(k+2)*3+1] + hv.w*wd_s[(k+3)*3+1];
        a2 += hv.x*wd_s[(k+0)*3+2] + hv.y*wd_s[(k+1)*3+2]
            + hv.z*wd_s[(k+2)*3+2] + hv.w*wd_s[(k+3)*3+2];
    }
    float mx  = fmaxf(a0, fmaxf(a1, a2));
    float lse = mx + logf(expf(a0 - mx) + expf(a1 - mx) + expf(a2 - mx));
    int   lab = labels[b];
    float sel = (lab == 0) ? a0 : ((lab == 1) ? a1 : a2);
    float nll = lse - sel;

    int off = (out_size >= 385) ? 1 : 0;
    if (out_size >= 384) {
        out[off + b*3 + 0] = a0;
        out[off + b*3 + 1] = a1;
        out[off + b*3 + 2] = a2;
    }
    red[b] = nll;
    __syncthreads();
    for (int s = 64; s; s >>= 1) {
        if (b < s) red[b] += red[b + s];
        __syncthreads();
    }
    if (b == 0 && (off == 1 || out_size < 384)) out[0] = red[0] * (1.f / 128.f);
}

// ---------------------------------------------------------------------------
extern "C" void kernel_launch(void* const* d_in, const int* in_sizes, int n_in,
                              void* d_out, int out_size)
{
    const int*   ids     = (const int*)  d_in[0];
    const int*   lengths = (const int*)  d_in[1];
    const int*   labels  = (const int*)  d_in[2];
    const float* emb     = (const float*)d_in[3];
    const float* W       = (const float*)d_in[4];
    const float* bl      = (const float*)d_in[5];
    const float* Wd      = (const float*)d_in[6];
    const float* bd      = (const float*)d_in[7];
    float* out = (float*)d_out;

    init_kernel<<<(BB*HH + 255)/256, 256>>>();
    precompute_kernel<<<dim3(19, 4, BB), 256>>>(ids, lengths, emb, W, bl);
    lstm_persistent<<<NCTAS, 256>>>(W, lengths);
    final_kernel<<<1, 128>>>(Wd, bd, labels, lengths, out, out_size);
}